// round 16
// baseline (speedup 1.0000x reference)
#include <cuda_runtime.h>
#include <cuda_bf16.h>
#include <cstdint>

// Problem constants
#define BB 32
#define NN 128
#define HH 128
#define HD 256
#define NHEADS 4
#define DH 64

// Scratch layout (floats)
#define OFF_BASE 0u
#define OFF_X0   524288u
#define OFF_Q    1048576u
#define OFF_K    2097152u
#define OFF_V    3145728u
#define OFF_S    4194304u
#define OFF_X1   5242880u
#define OFF_X2   6291456u
#define OFF_PART 7340032u   // 4 * 32 * 128 * 128 floats
#define OFF_CNT  9437184u   // 4 * 32 * 128 floats
#define OFF_WF   9453568u   // fragment-packed proj weights (393216 floats)
#define OFF_ADJT 9846784u   // transposed adj (524288 floats)
#define OFF_LIST 10371072u  // compacted pair lists (128 CTAs x 4096 u32)
#define SCRATCH_TOTAL 10895360u

__device__ float g_scratch[SCRATCH_TOTAL];

// ---------------------------------------------------------------------------
// PTX helpers (generic sm_80+ instructions only)
// ---------------------------------------------------------------------------
__device__ __forceinline__ uint32_t smem_u32(const void* p) {
    uint32_t a;
    asm("{ .reg .u64 t; cvta.to.shared.u64 t, %1; cvt.u32.u64 %0, t; }" : "=r"(a) : "l"(p));
    return a;
}
__device__ __forceinline__ void ldsm_x4(uint32_t& r0, uint32_t& r1, uint32_t& r2, uint32_t& r3, uint32_t addr) {
    asm volatile("ldmatrix.sync.aligned.m8n8.x4.shared.b16 {%0,%1,%2,%3}, [%4];"
                 : "=r"(r0), "=r"(r1), "=r"(r2), "=r"(r3) : "r"(addr));
}
__device__ __forceinline__ void mma_bf16(float* c, const uint32_t* a, uint32_t b0, uint32_t b1) {
    asm volatile("mma.sync.aligned.m16n8k16.row.col.f32.bf16.bf16.f32 "
                 "{%0,%1,%2,%3}, {%4,%5,%6,%7}, {%8,%9}, {%0,%1,%2,%3};"
                 : "+f"(c[0]), "+f"(c[1]), "+f"(c[2]), "+f"(c[3])
                 : "r"(a[0]), "r"(a[1]), "r"(a[2]), "r"(a[3]), "r"(b0), "r"(b1));
}
__device__ __forceinline__ uint32_t pack_hi2(float a, float b) {
    return (uint32_t)__bfloat16_as_ushort(__float2bfloat16(a))
         | ((uint32_t)__bfloat16_as_ushort(__float2bfloat16(b)) << 16);
}
__device__ __forceinline__ uint32_t pack_lo2(float a, float b) {
    float ra = a - __bfloat162float(__float2bfloat16(a));
    float rb = b - __bfloat162float(__float2bfloat16(b));
    return (uint32_t)__bfloat16_as_ushort(__float2bfloat16(ra))
         | ((uint32_t)__bfloat16_as_ushort(__float2bfloat16(rb)) << 16);
}

// ---------------------------------------------------------------------------
// Kernel 0a: pre-split proj weights into fragment-packed global layout.
// ---------------------------------------------------------------------------
__global__ void k_wsplit(const float* __restrict__ Wq1, const float* __restrict__ Wk1,
                         const float* __restrict__ Wv1, const float* __restrict__ Ws1,
                         const float* __restrict__ Wq2, const float* __restrict__ Wk2,
                         const float* __restrict__ Wv2, const float* __restrict__ Ws2) {
    unsigned idx = blockIdx.x * 256u + threadIdx.x;
    if (idx >= 98304u) return;
    const float* W;
    unsigned base, rem;
    if (idx < 32768u) {
        int mat = idx >> 13; rem = idx & 8191u;
        W = (mat == 0) ? Wq1 : (mat == 1) ? Wk1 : (mat == 2) ? Wv1 : Ws1;
        base = OFF_WF + (unsigned)mat * 32768u;
    } else {
        unsigned j = idx - 32768u;
        int mat = j >> 14; rem = j & 16383u;
        W = (mat == 0) ? Wq2 : (mat == 1) ? Wk2 : (mat == 2) ? Wv2 : Ws2;
        base = OFF_WF + 131072u + (unsigned)mat * 65536u;
    }
    int KT = (idx < 32768u) ? 8 : 16;
    int lane = rem & 31;
    int tile = rem >> 5;
    int kt = tile % KT;
    int nt = tile / KT;
    int n = nt * 8 + (lane >> 2);
    int k0 = kt * 16 + (lane & 3) * 2;
    float w00 = W[(unsigned)k0 * HD + n],       w01 = W[(unsigned)(k0 + 1) * HD + n];
    float w10 = W[(unsigned)(k0 + 8) * HD + n], w11 = W[(unsigned)(k0 + 9) * HD + n];
    uint4 out;
    out.x = pack_hi2(w00, w01); out.y = pack_hi2(w10, w11);
    out.z = pack_lo2(w00, w01); out.w = pack_lo2(w10, w11);
    *(uint4*)(g_scratch + base + (unsigned)rem * 4u) = out;
}

// ---------------------------------------------------------------------------
// Kernel 0b: transpose adj -> adjT[b][t][s]
// ---------------------------------------------------------------------------
__global__ void k_adjT(const float* __restrict__ adj) {
    __shared__ float tl[32][33];
    int b = blockIdx.z;
    int s0 = blockIdx.y * 32, t0 = blockIdx.x * 32;
    int x = threadIdx.x, y = threadIdx.y;
#pragma unroll
    for (int i = y; i < 32; i += 8)
        tl[i][x] = adj[(unsigned)(b * NN + s0 + i) * NN + t0 + x];
    __syncthreads();
#pragma unroll
    for (int i = y; i < 32; i += 8)
        g_scratch[OFF_ADJT + (unsigned)(b * NN + t0 + i) * NN + s0 + x] = tl[x][i];
}

// ---------------------------------------------------------------------------
// Kernel 1: base[b,s,j]
// ---------------------------------------------------------------------------
__global__ void k_base(const float* __restrict__ nf, const int* __restrict__ et,
                       const float* __restrict__ emb, const float* __restrict__ W1,
                       const float* __restrict__ b1) {
    int bn = blockIdx.x;
    int j  = threadIdx.x;
    const float* f = nf + bn * 9;
    const float* em = emb + et[bn] * 8;
    float acc = b1[j];
#pragma unroll
    for (int i = 0; i < 9; i++) acc += f[i] * W1[i * HH + j];
#pragma unroll
    for (int i = 0; i < 8; i++) acc += em[i] * W1[(9 + i) * HH + j];
    g_scratch[OFF_BASE + bn * HH + j] = acc;
}

// ---------------------------------------------------------------------------
// Kernel 2 (compacted embed): per (b, 32-s chunk), build a compacted list of
// active (s,t) pairs (~2048), run ceil(L/128) dense GEMMs over packed 128-row
// tiles. Output scatter-accumulated into SMEM x0acc via atomicAdd.
// ---------------------------------------------------------------------------
#define PK 136
#define SM2_BHI   0
#define SM2_BLO   34816
#define SM2_AHI   69632
#define SM2_ALO   104448
#define SM2_XACC  139264
#define SM2_BASE  204800
#define SM2_ROWS  221184
#define SM2_AVAL  221696
#define SM2_CNT   222208
#define SM2_RED   222720
#define SM2_W17   224768
#define SM2_G1    225280
#define SM2_BE1   225792
#define SM2_BH    226304
#define SM2_SCAN  226816
#define EMB2_SMEM 226880

__global__ void __launch_bounds__(256, 1)
k_embed_cmp(const float* __restrict__ adj, const float* __restrict__ W1,
            const float* __restrict__ g1, const float* __restrict__ be1,
            const float* __restrict__ Wh, const float* __restrict__ bh) {
    extern __shared__ char sm[];
    uint32_t smb = smem_u32(sm);
    float* sW17  = (float*)(sm + SM2_W17);
    float* sG1   = (float*)(sm + SM2_G1);
    float* sBe1  = (float*)(sm + SM2_BE1);
    float* sBh   = (float*)(sm + SM2_BH);
    float* XACC  = (float*)(sm + SM2_XACC);
    float* sBase = (float*)(sm + SM2_BASE);
    uint32_t* sRows = (uint32_t*)(sm + SM2_ROWS);
    float* sAval = (float*)(sm + SM2_AVAL);
    float* sCnt  = (float*)(sm + SM2_CNT);
    float2* sRed = (float2*)(sm + SM2_RED);
    unsigned* sScan = (unsigned*)(sm + SM2_SCAN);

    int tid = threadIdx.x, lane = tid & 31, wid = tid >> 5;
    int chunk = blockIdx.x, b = blockIdx.y;

    if (tid < 128) {
        sW17[tid] = W1[17 * HH + tid];
        sG1[tid]  = g1[tid];
        sBe1[tid] = be1[tid];
        sBh[tid]  = bh[tid];
        sCnt[tid] = 0.f;
    }

    // B = Wh^T as [j][k], hi/lo bf16
    for (int idx = tid; idx < 16384; idx += 256) {
        int k = idx >> 7, j = idx & 127;
        float w = Wh[idx];
        __nv_bfloat16 h = __float2bfloat16(w);
        __nv_bfloat16 l = __float2bfloat16(w - __bfloat162float(h));
        *(__nv_bfloat16*)(sm + SM2_BHI + (j * PK + k) * 2) = h;
        *(__nv_bfloat16*)(sm + SM2_BLO + (j * PK + k) * 2) = l;
    }
    // base rows for the chunk's 32 s
    for (int idx = tid; idx < 4096; idx += 256) {
        int s = idx >> 7, j = idx & 127;
        sBase[idx] = g_scratch[OFF_BASE + (unsigned)(b * NN + chunk * 32 + s) * HH + j];
    }
    // zero accumulator
    for (int idx = tid; idx < 16384; idx += 256) XACC[idx] = 0.f;

    // ---- Compaction: pair p = s*128 + t (s local 0..31) ----
    unsigned am = 0, cnt = 0;
    unsigned p0 = (unsigned)tid * 16u;
#pragma unroll
    for (int i = 0; i < 16; i++) {
        unsigned p = p0 + i;
        int s = (int)(p >> 7), t = (int)(p & 127u);
        float a = adj[(unsigned)(b * NN + chunk * 32 + s) * NN + t];
        bool mk = (a > 0.f) && (a < 1.0f);
        am |= ((unsigned)mk) << i;
        cnt += (unsigned)mk;
    }
    unsigned v = cnt;
#pragma unroll
    for (int o = 1; o < 32; o <<= 1) {
        unsigned n = __shfl_up_sync(0xffffffffu, v, o);
        if (lane >= o) v += n;
    }
    if (lane == 31) sScan[wid] = v;
    __syncthreads();
    if (tid == 0) {
        unsigned run = 0;
#pragma unroll
        for (int i = 0; i < 8; i++) { unsigned w = sScan[i]; sScan[i] = run; run += w; }
        sScan[8] = run;
    }
    __syncthreads();
    unsigned woff = v - cnt + sScan[wid];
    unsigned L = sScan[8];
    uint32_t* glist = (uint32_t*)g_scratch + OFF_LIST + (unsigned)(chunk * BB + b) * 4096u;
#pragma unroll
    for (int i = 0; i < 16; i++) {
        if ((am >> i) & 1u) glist[woff++] = p0 + i;
    }
    __syncthreads();

    int nG = (int)((L + 127u) >> 7);

    // MMA layout (R10 proven): 4m x 2n, warp tile 32 rows x 64 cols
    int mrow = wid & 3, ncol = wid >> 2;
    int m0 = mrow * 32;
    int rA0 = m0 + (lane >> 2);
    int colbase = ncol * 64;
    uint32_t aoff0 = (uint32_t)((m0 + (lane & 15)) * PK + (lane >> 4) * 8) * 2;
    const uint32_t MT_STRIDE = (uint32_t)(16 * PK * 2);
    uint32_t brow = (uint32_t)(((lane & 16) >> 1) + (lane & 7));
    uint32_t bk   = (uint32_t)(((lane >> 3) & 1) * 8);
    int tA = tid >> 1, half = tid & 1;

    for (int g = 0; g < nG; g++) {
        // ---- Row cache for this GEMM ----
        if (tid < 128) {
            unsigned p = (unsigned)g * 128u + (unsigned)tid;
            unsigned rc; float a = 0.f;
            if (p < L) {
                unsigned pt = glist[p];
                unsigned s = pt >> 7, t = pt & 127u;
                a = adj[(unsigned)(b * NN + chunk * 32 + (int)s) * NN + (int)t];
                rc = 0x10000u | (s << 8) | t;
            } else {
                rc = (unsigned)tid;   // valid=0
            }
            sRows[tid] = rc;
            sAval[tid] = a;
        }
        __syncthreads();

        // ---- Build A row tA (cols [half*64, +64)) ----
        {
            unsigned rc = sRows[tA];
            unsigned sl = (rc >> 8) & 31u;
            float at = sAval[tA];
            const float* basep = sBase + sl * 128u;
            int c0 = half * 64;
            float sum = 0.f, ssum = 0.f;
#pragma unroll 4
            for (int j = 0; j < 64; j++) {
                float y = fmaxf(basep[c0 + j] + at * sW17[c0 + j], 0.f);
                sum += y; ssum += y * y;
            }
            sum  += __shfl_xor_sync(0xffffffffu, sum, 1);
            ssum += __shfl_xor_sync(0xffffffffu, ssum, 1);
            float mean = sum * (1.f / 128.f);
            float rs = rsqrtf(ssum * (1.f / 128.f) - mean * mean + 1e-5f);
#pragma unroll 2
            for (int j2 = 0; j2 < 32; j2++) {
                int j = c0 + j2 * 2;
                float y0 = fmaxf(basep[j] + at * sW17[j], 0.f);
                float y1 = fmaxf(basep[j + 1] + at * sW17[j + 1], 0.f);
                float h0 = (y0 - mean) * rs * sG1[j] + sBe1[j];
                float h1 = (y1 - mean) * rs * sG1[j + 1] + sBe1[j + 1];
                uint32_t off = (uint32_t)(tA * PK + j) * 2;
                *(uint32_t*)(sm + SM2_AHI + off) = pack_hi2(h0, h1);
                *(uint32_t*)(sm + SM2_ALO + off) = pack_lo2(h0, h1);
            }
        }
        __syncthreads();

        // ---- MMA: 32 rows x 64 cols per warp ----
        float c[64];
#pragma unroll
        for (int u = 0; u < 64; u++) c[u] = 0.f;

#pragma unroll
        for (int kk = 0; kk < 8; kk++) {
            uint32_t ka = aoff0 + (uint32_t)(kk * 16) * 2;
            uint32_t ah0[4], al0[4], ah1[4], al1[4];
            ldsm_x4(ah0[0], ah0[1], ah0[2], ah0[3], smb + SM2_AHI + ka);
            ldsm_x4(al0[0], al0[1], al0[2], al0[3], smb + SM2_ALO + ka);
            ldsm_x4(ah1[0], ah1[1], ah1[2], ah1[3], smb + SM2_AHI + ka + MT_STRIDE);
            ldsm_x4(al1[0], al1[1], al1[2], al1[3], smb + SM2_ALO + ka + MT_STRIDE);
#pragma unroll
            for (int jp = 0; jp < 4; jp++) {
                uint32_t boff = (uint32_t)((colbase + jp * 16 + brow) * PK + kk * 16 + bk) * 2;
                uint32_t bh4[4], bl4[4];
                ldsm_x4(bh4[0], bh4[1], bh4[2], bh4[3], smb + SM2_BHI + boff);
                ldsm_x4(bl4[0], bl4[1], bl4[2], bl4[3], smb + SM2_BLO + boff);
                {
                    float* ca = c + (jp * 2) * 4;
                    float* cb = c + (jp * 2 + 1) * 4;
                    mma_bf16(ca, ah0, bh4[0], bh4[1]);
                    mma_bf16(ca, al0, bh4[0], bh4[1]);
                    mma_bf16(ca, ah0, bl4[0], bl4[1]);
                    mma_bf16(cb, ah0, bh4[2], bh4[3]);
                    mma_bf16(cb, al0, bh4[2], bh4[3]);
                    mma_bf16(cb, ah0, bl4[2], bl4[3]);
                }
                {
                    float* ca = c + 32 + (jp * 2) * 4;
                    float* cb = c + 32 + (jp * 2 + 1) * 4;
                    mma_bf16(ca, ah1, bh4[0], bh4[1]);
                    mma_bf16(ca, al1, bh4[0], bh4[1]);
                    mma_bf16(ca, ah1, bl4[0], bl4[1]);
                    mma_bf16(cb, ah1, bh4[2], bh4[3]);
                    mma_bf16(cb, al1, bh4[2], bh4[3]);
                    mma_bf16(cb, ah1, bl4[2], bl4[3]);
                }
            }
        }

        // ---- Epilogue part 1: relu(+bh), per-64-col partial sums ----
        float psumA[2], pssA[2], psumB[2], pssB[2];
#pragma unroll
        for (int mt = 0; mt < 2; mt++) {
            float sum0 = 0.f, ss0 = 0.f, sum1 = 0.f, ss1 = 0.f;
#pragma unroll
            for (int jt = 0; jt < 8; jt++) {
                int col = colbase + jt * 8 + (lane & 3) * 2;
                float b0 = sBh[col], b1 = sBh[col + 1];
                int ci = (mt * 8 + jt) * 4;
                float e0 = fmaxf(c[ci + 0] + b0, 0.f);
                float e1 = fmaxf(c[ci + 1] + b1, 0.f);
                float e2 = fmaxf(c[ci + 2] + b0, 0.f);
                float e3 = fmaxf(c[ci + 3] + b1, 0.f);
                c[ci + 0] = e0; c[ci + 1] = e1; c[ci + 2] = e2; c[ci + 3] = e3;
                sum0 += e0 + e1; ss0 += e0 * e0 + e1 * e1;
                sum1 += e2 + e3; ss1 += e2 * e2 + e3 * e3;
            }
#pragma unroll
            for (int o = 1; o <= 2; o <<= 1) {
                sum0 += __shfl_xor_sync(0xffffffffu, sum0, o);
                ss0  += __shfl_xor_sync(0xffffffffu, ss0, o);
                sum1 += __shfl_xor_sync(0xffffffffu, sum1, o);
                ss1  += __shfl_xor_sync(0xffffffffu, ss1, o);
            }
            psumA[mt] = sum0; pssA[mt] = ss0;
            psumB[mt] = sum1; pssB[mt] = ss1;
        }
        if ((lane & 3) == 0) {
#pragma unroll
            for (int mt = 0; mt < 2; mt++) {
                int rA = rA0 + mt * 16, rB = rA + 8;
                sRed[rA * 2 + ncol] = make_float2(psumA[mt], pssA[mt]);
                sRed[rB * 2 + ncol] = make_float2(psumB[mt], pssB[mt]);
            }
        }
        __syncthreads();

        // ---- Epilogue part 2: full-row LN + scatter into XACC ----
#pragma unroll
        for (int mt = 0; mt < 2; mt++) {
            int rA = rA0 + mt * 16, rB = rA + 8;
            float2 a0 = sRed[rA * 2 + 0], a1 = sRed[rA * 2 + 1];
            float2 b0v = sRed[rB * 2 + 0], b1v = sRed[rB * 2 + 1];
            float sumA = a0.x + a1.x, ssA = a0.y + a1.y;
            float sumB = b0v.x + b1v.x, ssB = b0v.y + b1v.y;
            float meanA = sumA * (1.f / 128.f);
            float rsA = rsqrtf(ssA * (1.f / 128.f) - meanA * meanA + 1e-5f);
            float meanB = sumB * (1.f / 128.f);
            float rsB = rsqrtf(ssB * (1.f / 128.f) - meanB * meanB + 1e-5f);
            unsigned rcA = sRows[rA], rcB = sRows[rB];
            bool vA = (rcA >> 16) != 0, vB = (rcB >> 16) != 0;
            unsigned tAo = rcA & 127u, tBo = rcB & 127u;
#pragma unroll
            for (int jt = 0; jt < 8; jt++) {
                int col = colbase + jt * 8 + (lane & 3) * 2;
                int ci = (mt * 8 + jt) * 4;
                if (vA) {
                    atomicAdd(&XACC[tAo * 128u + col],     (c[ci + 0] - meanA) * rsA);
                    atomicAdd(&XACC[tAo * 128u + col + 1], (c[ci + 1] - meanA) * rsA);
                }
                if (vB) {
                    atomicAdd(&XACC[tBo * 128u + col],     (c[ci + 2] - meanB) * rsB);
                    atomicAdd(&XACC[tBo * 128u + col + 1], (c[ci + 3] - meanB) * rsB);
                }
            }
            if (ncol == 0 && (lane & 3) == 0) {
                if (vA) atomicAdd(&sCnt[tAo], 1.f);
                if (vB) atomicAdd(&sCnt[tBo], 1.f);
            }
        }
        __syncthreads();   // all reads of A / sRows done before next iteration
    }

    // ---- Write partials ----
    unsigned pbase_o = OFF_PART + (unsigned)(chunk * 32 + b) * 16384u;
    for (int idx = tid; idx < 16384; idx += 256)
        g_scratch[pbase_o + idx] = XACC[idx];
    if (tid < 128)
        g_scratch[OFF_CNT + (unsigned)(chunk * 32 + b) * 128u + tid] = sCnt[tid];
}

// ---------------------------------------------------------------------------
// Kernel 2b: combine partials + outer-LN affine -> x0
// ---------------------------------------------------------------------------
__global__ void k_combine(const float* __restrict__ gh, const float* __restrict__ beh) {
    int bt = blockIdx.x;
    int j = threadIdx.x;
    float v = 0.f, c = 0.f;
#pragma unroll
    for (int q = 0; q < 4; q++) {
        v += g_scratch[OFF_PART + (unsigned)q * 524288u + (unsigned)bt * 128u + j];
        c += g_scratch[OFF_CNT + (unsigned)q * 4096u + bt];
    }
    g_scratch[OFF_X0 + (unsigned)bt * 128u + j] = gh[j] * v + beh[j] * c;
}

// ---------------------------------------------------------------------------
// Kernel 3 (HMMA proj, B fragments from global) — unchanged (proven)
// ---------------------------------------------------------------------------
template <int HIN>
__global__ void __launch_bounds__(256, 1)
k_proj_mma(unsigned xoff, unsigned wfoff,
           const float* __restrict__ bq, const float* __restrict__ bk,
           const float* __restrict__ bv, const float* __restrict__ bs) {
    extern __shared__ char sm[];
    constexpr int PJ = HIN + 8;
    constexpr int XHI = 0;
    constexpr int XLO = XHI + 64 * PJ * 2;
    constexpr int KT = HIN / 16;
    constexpr int RSH = (HIN == 128) ? 7 : 8;

    uint32_t smb = smem_u32(sm);
    int tid = threadIdx.x, lane = tid & 31, wid = tid >> 5;
    int r0 = blockIdx.x * 64;
    int my = blockIdx.y;
    const float* bias = (my == 0) ? bq : (my == 1) ? bk : (my == 2) ? bv : bs;
    unsigned outoff   = (my == 0) ? OFF_Q : (my == 1) ? OFF_K : (my == 2) ? OFF_V : OFF_S;
    const float* x = g_scratch + xoff;
    const uint4* BF = (const uint4*)(g_scratch + wfoff + (unsigned)my * (32u * KT * 32u * 4u));

    for (int idx = tid; idx < 64 * HIN; idx += 256) {
        int r = idx >> RSH, k = idx & (HIN - 1);
        float v = x[(unsigned)(r0 + r) * HIN + k];
        __nv_bfloat16 h = __float2bfloat16(v);
        __nv_bfloat16 l = __float2bfloat16(v - __bfloat162float(h));
        *(__nv_bfloat16*)(sm + XHI + (r * PJ + k) * 2) = h;
        *(__nv_bfloat16*)(sm + XLO + (r * PJ + k) * 2) = l;
    }
    __syncthreads();

    int mrow = wid & 3, ncol = wid >> 2;
    int m0 = mrow * 16;
    uint32_t aoff = (uint32_t)((m0 + (lane & 15)) * PJ + (lane >> 4) * 8) * 2;

    float c[64];
#pragma unroll
    for (int u = 0; u < 64; u++) c[u] = 0.f;

#pragma unroll
    for (int kk = 0; kk < KT; kk++) {
        uint32_t ah[4], al[4];
        uint32_t ka = aoff + (uint32_t)(kk * 16) * 2;
        ldsm_x4(ah[0], ah[1], ah[2], ah[3], smb + XHI + ka);
        ldsm_x4(al[0], al[1], al[2], al[3], smb + XLO + ka);
#pragma unroll
        for (int jp = 0; jp < 16; jp++) {
            int nt = ncol * 16 + jp;
            uint4 f = BF[(unsigned)(nt * KT + kk) * 32u + lane];
            float* cj = c + jp * 4;
            mma_bf16(cj, ah, f.x, f.y);
            mma_bf16(cj, al, f.x, f.y);
            mma_bf16(cj, ah, f.z, f.w);
        }
    }

    int rA = r0 + m0 + (lane >> 2);
    int rB = rA + 8;
#pragma unroll
    for (int jp = 0; jp < 16; jp++) {
        int col = ncol * 128 + jp * 8 + (lane & 3) * 2;
        float b0 = bias[col], b1 = bias[col + 1];
        *(float2*)(g_scratch + outoff + (unsigned)rA * HD + col) =
            make_float2(c[jp * 4 + 0] + b0, c[jp * 4 + 1] + b1);
        *(float2*)(g_scratch + outoff + (unsigned)rB * HD + col) =
            make_float2(c[jp * 4 + 2] + b0, c[jp * 4 + 3] + b1);
    }
}

// ---------------------------------------------------------------------------
// Kernel 4 (HMMA attention) — unchanged from Round 14 (proven)
// ---------------------------------------------------------------------------
#define AQHI 0
#define AQLO 18432
#define AKHI 36864
#define AKLO 55296
#define AVHI 73728
#define AVLO 91136
#define APHI 108544
#define APLO 143360
#define AQE  178176
#define ABETA 178688
#define AWE  179200
#define ATTN_SMEM 179456

__global__ void __launch_bounds__(128, 1)
k_attn_mma(const float* __restrict__ we, unsigned outoff) {
    extern __shared__ char sm[];
    uint32_t smb = smem_u32(sm);
    float* sQE   = (float*)(sm + AQE);
    float* sBeta = (float*)(sm + ABETA);
    float* sWe   = (float*)(sm + AWE);

    int h = blockIdx.x, b = blockIdx.y;
    int tid = threadIdx.x, lane = tid & 31, wid = tid >> 5;
    const float* q = g_scratch + OFF_Q;
    const float* k = g_scratch + OFF_K;
    const float* v = g_scratch + OFF_V;
    const float* skip = g_scratch + OFF_S;
    const float* adjT = g_scratch + OFF_ADJT + (unsigned)b * NN * NN;
    float* xout = g_scratch + outoff;

    if (tid < 64) sWe[tid] = we[h * DH + tid];
    for (int idx = tid; idx < 8192; idx += 128) {
        int r = idx >> 6, d = idx & 63;
        unsigned g = ((unsigned)(b * NN + r) * NHEADS + h) * DH + d;
        float qv = q[g], kv = k[g], vv = v[g];
        __nv_bfloat16 qh = __float2bfloat16(qv);
        __nv_bfloat16 kh = __float2bfloat16(kv);
        __nv_bfloat16 vh = __float2bfloat16(vv);
        *(__nv_bfloat16*)(sm + AQHI + (r * 72 + d) * 2) = qh;
        *(__nv_bfloat16*)(sm + AQLO + (r * 72 + d) * 2) = __float2bfloat16(qv - __bfloat162float(qh));
        *(__nv_bfloat16*)(sm + AKHI + (r * 72 + d) * 2) = kh;
        *(__nv_bfloat16*)(sm + AKLO + (r * 72 + d) * 2) = __float2bfloat16(kv - __bfloat162float(kh));
        *(__nv_bfloat16*)(sm + AVHI + (d * PK + r) * 2) = vh;
        *(__nv_bfloat16*)(sm + AVLO + (d * PK + r) * 2) = __float2bfloat16(vv - __bfloat162float(vh));
    }
    __syncthreads();

    {
        int t = tid;
        float acc = 0.f;
#pragma unroll 8
        for (int d = 0; d < 64; d++) {
            float hv = __bfloat162float(*(__nv_bfloat16*)(sm + AQHI + (t * 72 + d) * 2));
            float lv = __bfloat162float(*(__nv_bfloat16*)(sm + AQLO + (t * 72 + d) * 2));
            acc += (hv + lv) * sWe[d];
        }
        sQE[t] = acc;
    }
    __syncthreads();

    uint32_t brow = (uint32_t)(((lane & 16) >> 1) + (lane & 7));
    uint32_t bk   = (uint32_t)(((lane >> 3) & 1) * 8);
    const float scale = 0.125f;

#pragma unroll 1
    for (int tpass = 0; tpass < 2; tpass++) {
        int m0 = tpass * 64 + wid * 16;
        int r0 = m0 + (lane >> 2), r1 = r0 + 8;
        uint32_t aoff = (uint32_t)((m0 + (lane & 15)) * 72 + (lane >> 4) * 8) * 2;

        float c[64];
#pragma unroll
        for (int u = 0; u < 64; u++) c[u] = 0.f;

#pragma unroll
        for (int kk = 0; kk < 4; kk++) {
            uint32_t ka = aoff + (uint32_t)(kk * 16) * 2;
            uint32_t ah[4], al[4];
            ldsm_x4(ah[0], ah[1], ah[2], ah[3], smb + AQHI + ka);
            ldsm_x4(al[0], al[1], al[2], al[3], smb + AQLO + ka);
#pragma unroll
            for (int jp = 0; jp < 8; jp++) {
                uint32_t boff = (uint32_t)((jp * 16 + brow) * 72 + kk * 16 + bk) * 2;
                uint32_t bh4[4], bl4[4];
                ldsm_x4(bh4[0], bh4[1], bh4[2], bh4[3], smb + AKHI + boff);
                ldsm_x4(bl4[0], bl4[1], bl4[2], bl4[3], smb + AKLO + boff);
                float* ca = c + (jp * 2) * 4;
                float* cb = c + (jp * 2 + 1) * 4;
                mma_bf16(ca, ah, bh4[0], bh4[1]);
                mma_bf16(cb, ah, bh4[2], bh4[3]);
                mma_bf16(ca, al, bh4[0], bh4[1]);
                mma_bf16(cb, al, bh4[2], bh4[3]);
                mma_bf16(ca, ah, bl4[0], bl4[1]);
                mma_bf16(cb, ah, bl4[2], bl4[3]);
            }
        }

        float av[64];
        float qe0 = sQE[r0], qe1 = sQE[r1];
#pragma unroll
        for (int jt = 0; jt < 16; jt++) {
            int col = jt * 8 + (lane & 3) * 2;
            float2 a0 = *(const float2*)(adjT + (unsigned)r0 * NN + col);
            float2 a1 = *(const float2*)(adjT + (unsigned)r1 * NN + col);
            int ci = jt * 4;
            bool m00 = (a0.x > 0.f) && (a0.x < 1.0f);
            bool m01 = (a0.y > 0.f) && (a0.y < 1.0f);
            bool m10 = (a1.x > 0.f) && (a1.x < 1.0f);
            bool m11 = (a1.y > 0.f) && (a1.y < 1.0f);
            float v00 = m00 ? a0.x : 0.f, v01 = m01 ? a0.y : 0.f;
            float v10 = m10 ? a1.x : 0.f, v11 = m11 ? a1.y : 0.f;
            av[ci + 0] = v00; av[ci + 1] = v01; av[ci + 2] = v10; av[ci + 3] = v11;
            c[ci + 0] = m00 ? (c[ci + 0] + v00 * qe0) * scale : -1e30f;
            c[ci + 1] = m01 ? (c[ci + 1] + v01 * qe0) * scale : -1e30f;
            c[ci + 2] = m10 ? (c[ci + 2] + v10 * qe1) * scale : -1e30f;
            c[ci + 3] = m11 ? (c[ci + 3] + v11 * qe1) * scale : -1e30f;
        }

        float mx0 = -1e30f, mx1 = -1e30f;
#pragma unroll
        for (int jt = 0; jt < 16; jt++) {
            mx0 = fmaxf(mx0, fmaxf(c[jt * 4 + 0], c[jt * 4 + 1]));
            mx1 = fmaxf(mx1, fmaxf(c[jt * 4 + 2], c[jt * 4 + 3]));
        }
#pragma unroll
        for (int o = 1; o <= 2; o <<= 1) {
            mx0 = fmaxf(mx0, __shfl_xor_sync(0xffffffffu, mx0, o));
            mx1 = fmaxf(mx1, __shfl_xor_sync(0xffffffffu, mx1, o));
        }

        float sw0 = 0.f, swa0 = 0.f, sw1 = 0.f, swa1 = 0.f;
#pragma unroll
        for (int jt = 0; jt < 16; jt++) {
            int ci = jt * 4;
            float w0 = (c[ci + 0] > -1e29f) ? __expf(c[ci + 0] - mx0) : 0.f;
            float w1 = (c[ci + 1] > -1e29f) ? __expf(c[ci + 1] - mx0) : 0.f;
            float w2 = (c[ci + 2] > -1e29f) ? __expf(c[ci + 2] - mx1) : 0.f;
            float w3 = (c[ci + 3] > -1e29f) ? __expf(c[ci + 3] - mx1) : 0.f;
            c[ci + 0] = w0; c[ci + 1] = w1; c[ci + 2] = w2; c[ci + 3] = w3;
            sw0 += w0 + w1; swa0 += w0 * av[ci + 0] + w1 * av[ci + 1];
            sw1 += w2 + w3; swa1 += w2 * av[ci + 2] + w3 * av[ci + 3];
        }
#pragma unroll
        for (int o = 1; o <= 2; o <<= 1) {
            sw0  += __shfl_xor_sync(0xffffffffu, sw0, o);
            swa0 += __shfl_xor_sync(0xffffffffu, swa0, o);
            sw1  += __shfl_xor_sync(0xffffffffu, sw1, o);
            swa1 += __shfl_xor_sync(0xffffffffu, swa1, o);
        }
        float inv0 = 1.f / fmaxf(sw0, 1e-16f);
        float inv1 = 1.f / fmaxf(sw1, 1e-16f);
        if ((lane & 3) == 0) {
            sBeta[r0] = swa0 * inv0;
            sBeta[r1] = swa1 * inv1;
        }

#pragma unroll
        for (int jt = 0; jt < 16; jt++) {
            int col = jt * 8 + (lane & 3) * 2;
            int ci = jt * 4;
            float a00 = c[ci + 0] * inv0, a01 = c[ci + 1] * inv0;
            float a10 = c[ci + 2] * inv1, a11 = c[ci + 3] * inv1;
            uint32_t o0 = (uint32_t)(r0 * PK + col) * 2;
            uint32_t o1 = (uint32_t)(r1 * PK + col) * 2;
            *(uint32_t*)(sm + APHI + o0) = pack_hi2(a00, a01);
            *(uint32_t*)(sm + APLO + o0) = pack_lo2(a00, a01);
            *(uint32_t*)(sm + APHI + o1) = pack_hi2(a10, a11);
            *(uint32_t*)(sm + APLO + o1) = pack_lo2(a10, a11);
        }
    }
    __syncthreads();

    {
        int m0 = wid * 32;
        int r0 = m0 + (lane >> 2);
        uint32_t aoff = (uint32_t)((m0 + (lane & 15)) * PK + (lane >> 4) * 8) * 2;
        const uint32_t MTS = (uint32_t)(16 * PK * 2);

        float c[64];
#pragma unroll
        for (int u = 0; u < 64; u++) c[u] = 0.f;

#pragma unroll
        for (int kk = 0; kk < 8; kk++) {
            uint32_t ka = aoff + (uint32_t)(kk * 16) * 2;
            uint32_t ah0[4], al0[4], ah1[4], al1[4];
            ldsm_x4(ah0[0], ah0[1], ah0[2], ah0[3], smb + APHI + ka);
            ldsm_x4(al0[0], al0[1], al0[2], al0[3], smb + APLO + ka);
            ldsm_x4(ah1[0], ah1[1], ah1[2], ah1[3], smb + APHI + ka + MTS);
            ldsm_x4(al1[0], al1[1], al1[2], al1[3], smb + APLO + ka + MTS);
#pragma unroll
            for (int jp = 0; jp < 4; jp++) {
                uint32_t boff = (uint32_t)((jp * 16 + brow) * PK + kk * 16 + bk) * 2;
                uint32_t bh4[4], bl4[4];
                ldsm_x4(bh4[0], bh4[1], bh4[2], bh4[3], smb + AVHI + boff);
                ldsm_x4(bl4[0], bl4[1], bl4[2], bl4[3], smb + AVLO + boff);
                float* ca0 = c + (jp * 2) * 4;
                float* cb0 = c + (jp * 2 + 1) * 4;
                float* ca1 = c + 32 + (jp * 2) * 4;
                float* cb1 = c + 32 + (jp * 2 + 1) * 4;
                mma_bf16(ca0, ah0, bh4[0], bh4[1]);
                mma_bf16(cb0, ah0, bh4[2], bh4[3]);
                mma_bf16(ca1, ah1, bh4[0], bh4[1]);
                mma_bf16(cb1, ah1, bh4[2], bh4[3]);
                mma_bf16(ca0, al0, bh4[0], bh4[1]);
                mma_bf16(cb0, al0, bh4[2], bh4[3]);
                mma_bf16(ca1, al1, bh4[0], bh4[1]);
                mma_bf16(cb1, al1, bh4[2], bh4[3]);
                mma_bf16(ca0, ah0, bl4[0], bl4[1]);
                mma_bf16(cb0, ah0, bl4[2], bl4[3]);
                mma_bf16(ca1, ah1, bl4[0], bl4[1]);
                mma_bf16(cb1, ah1, bl4[2], bl4[3]);
            }
        }

#pragma unroll
        for (int mt = 0; mt < 2; mt++) {
            int rA = r0 + mt * 16, rB = rA + 8;
            float betaA = sBeta[rA], betaB = sBeta[rB];
#pragma unroll
            for (int jt = 0; jt < 8; jt++) {
                int col = jt * 8 + (lane & 3) * 2;
                float we0 = sWe[col], we1 = sWe[col + 1];
                int ci = (mt * 8 + jt) * 4;
                unsigned iA = (unsigned)(b * NN + rA) * HD + h * DH + col;
                unsigned iB = (unsigned)(b * NN + rB) * HD + h * DH + col;
                float2 skA = *(const float2*)(skip + iA);
                float2 skB = *(const float2*)(skip + iB);
                float oA0 = fmaxf(c[ci + 0] + betaA * we0 + skA.x, 0.f);
                float oA1 = fmaxf(c[ci + 1] + betaA * we1 + skA.y, 0.f);
                float oB0 = fmaxf(c[ci + 2] + betaB * we0 + skB.x, 0.f);
                float oB1 = fmaxf(c[ci + 3] + betaB * we1 + skB.y, 0.f);
                *(float2*)(xout + iA) = make_float2(oA0, oA1);
                *(float2*)(xout + iB) = make_float2(oB0, oB1);
            }
        }
    }
}

// ---------------------------------------------------------------------------
// Kernel 5: gather agent rows
// ---------------------------------------------------------------------------
__global__ void k_gather(const int* __restrict__ agent, float* __restrict__ out) {
    int b = blockIdx.x, j = threadIdx.x;
    out[b * HD + j] = g_scratch[OFF_X2 + (unsigned)(b * NN + agent[b]) * HD + j];
}

// ---------------------------------------------------------------------------
extern "C" void kernel_launch(void* const* d_in, const int* in_sizes, int n_in,
                              void* d_out, int out_size) {
    const float* node_feat = (const float*)d_in[0];
    const int*   entity_type = (const int*)d_in[1];
    const float* adj = (const float*)d_in[2];
    const int*   agent_id = (const int*)d_in[3];
    const float* emb = (const float*)d_in[4];
    const float* W1 = (const float*)d_in[5];
    const float* b1 = (const float*)d_in[6];
    const float* g1 = (const float*)d_in[7];
    const float* be1 = (const float*)d_in[8];
    const float* Wh = (const float*)d_in[9];
    const float* bh = (const float*)d_in[10];
    const float* gh = (const float*)d_in[11];
    const float* beh = (const float*)d_in[12];
    const float* Wq1 = (const float*)d_in[13];
    const float* bq1 = (const float*)d_in[14];
    const float* Wk1 = (const float*)d_in[15];
    const float* bk1 = (const float*)d_in[16];
    const float* Wv1 = (const float*)d_in[17];
    const float* bv1 = (const float*)d_in[18];
    const float* We1 = (const float*)d_in[19];
    const float* Ws1 = (const float*)d_in[20];
    const float* bs1 = (const float*)d_in[21];
    const float* Wq2 = (const float*)d_in[22];
    const float* bq2 = (const float*)d_in[23];
    const float* Wk2 = (const float*)d_in[24];
    const float* bk2 = (const float*)d_in[25];
    const float* Wv2 = (const float*)d_in[26];
    const float* bv2 = (const float*)d_in[27];
    const float* We2 = (const float*)d_in[28];
    const float* Ws2 = (const float*)d_in[29];
    const float* bs2 = (const float*)d_in[30];

    constexpr int PROJ128_SMEM = 2 * 64 * 136 * 2;   // 34816
    constexpr int PROJ256_SMEM = 2 * 64 * 264 * 2;   // 67584

    cudaFuncSetAttribute(k_embed_cmp, cudaFuncAttributeMaxDynamicSharedMemorySize, EMB2_SMEM);
    cudaFuncSetAttribute(k_proj_mma<128>, cudaFuncAttributeMaxDynamicSharedMemorySize, PROJ128_SMEM);
    cudaFuncSetAttribute(k_proj_mma<256>, cudaFuncAttributeMaxDynamicSharedMemorySize, PROJ256_SMEM);
    cudaFuncSetAttribute(k_attn_mma, cudaFuncAttributeMaxDynamicSharedMemorySize, ATTN_SMEM);

    k_wsplit<<<384, 256>>>(Wq1, Wk1, Wv1, Ws1, Wq2, Wk2, Wv2, Ws2);
    k_adjT<<<dim3(4, 4, BB), dim3(32, 8)>>>(adj);
    k_base<<<BB * NN, 128>>>(node_feat, entity_type, emb, W1, b1);
    k_embed_cmp<<<dim3(4, BB), 256, EMB2_SMEM>>>(adj, W1, g1, be1, Wh, bh);
    k_combine<<<BB * NN, 128>>>(gh, beh);

    k_proj_mma<128><<<dim3(64, 4), 256, PROJ128_SMEM>>>(OFF_X0, OFF_WF, bq1, bk1, bv1, bs1);
    k_attn_mma<<<dim3(NHEADS, BB), 128, ATTN_SMEM>>>(We1, OFF_X1);

    k_proj_mma<256><<<dim3(64, 4), 256, PROJ256_SMEM>>>(OFF_X1, OFF_WF + 131072u, bq2, bk2, bv2, bs2);
    k_attn_mma<<<dim3(NHEADS, BB), 128, ATTN_SMEM>>>(We2, OFF_X2);

    k_gather<<<BB, 256>>>(agent_id, (float*)d_out);
}

// round 17
// speedup vs baseline: 1.0986x; 1.0986x over previous
#include <cuda_runtime.h>
#include <cuda_bf16.h>
#include <cstdint>

// Problem constants
#define BB 32
#define NN 128
#define HH 128
#define HD 256
#define NHEADS 4
#define DH 64

// Scratch layout (floats)
#define OFF_BASE 0u
#define OFF_X0   524288u
#define OFF_Q    1048576u
#define OFF_K    2097152u
#define OFF_V    3145728u
#define OFF_S    4194304u
#define OFF_X1   5242880u
#define OFF_X2   6291456u
#define OFF_PART 7340032u   // 4 * 32 * 128 * 128 floats
#define OFF_CNT  9437184u   // 4 * 32 * 128 floats
#define OFF_WF   9453568u   // fragment-packed proj weights (393216 floats)
#define OFF_ADJT 9846784u   // transposed adj (524288 floats)
#define SCRATCH_TOTAL 10371072u

__device__ float g_scratch[SCRATCH_TOTAL];

// ---------------------------------------------------------------------------
// PTX helpers (generic sm_80+ instructions only)
// ---------------------------------------------------------------------------
__device__ __forceinline__ uint32_t smem_u32(const void* p) {
    uint32_t a;
    asm("{ .reg .u64 t; cvta.to.shared.u64 t, %1; cvt.u32.u64 %0, t; }" : "=r"(a) : "l"(p));
    return a;
}
__device__ __forceinline__ void ldsm_x4(uint32_t& r0, uint32_t& r1, uint32_t& r2, uint32_t& r3, uint32_t addr) {
    asm volatile("ldmatrix.sync.aligned.m8n8.x4.shared.b16 {%0,%1,%2,%3}, [%4];"
                 : "=r"(r0), "=r"(r1), "=r"(r2), "=r"(r3) : "r"(addr));
}
__device__ __forceinline__ void mma_bf16(float* c, const uint32_t* a, uint32_t b0, uint32_t b1) {
    asm volatile("mma.sync.aligned.m16n8k16.row.col.f32.bf16.bf16.f32 "
                 "{%0,%1,%2,%3}, {%4,%5,%6,%7}, {%8,%9}, {%0,%1,%2,%3};"
                 : "+f"(c[0]), "+f"(c[1]), "+f"(c[2]), "+f"(c[3])
                 : "r"(a[0]), "r"(a[1]), "r"(a[2]), "r"(a[3]), "r"(b0), "r"(b1));
}
__device__ __forceinline__ uint32_t pack_hi2(float a, float b) {
    return (uint32_t)__bfloat16_as_ushort(__float2bfloat16(a))
         | ((uint32_t)__bfloat16_as_ushort(__float2bfloat16(b)) << 16);
}
__device__ __forceinline__ uint32_t pack_lo2(float a, float b) {
    float ra = a - __bfloat162float(__float2bfloat16(a));
    float rb = b - __bfloat162float(__float2bfloat16(b));
    return (uint32_t)__bfloat16_as_ushort(__float2bfloat16(ra))
         | ((uint32_t)__bfloat16_as_ushort(__float2bfloat16(rb)) << 16);
}

// ---------------------------------------------------------------------------
// Kernel 0a: pre-split proj weights into fragment-packed global layout.
// ---------------------------------------------------------------------------
__global__ void k_wsplit(const float* __restrict__ Wq1, const float* __restrict__ Wk1,
                         const float* __restrict__ Wv1, const float* __restrict__ Ws1,
                         const float* __restrict__ Wq2, const float* __restrict__ Wk2,
                         const float* __restrict__ Wv2, const float* __restrict__ Ws2) {
    unsigned idx = blockIdx.x * 256u + threadIdx.x;
    if (idx >= 98304u) return;
    const float* W;
    unsigned base, rem;
    if (idx < 32768u) {
        int mat = idx >> 13; rem = idx & 8191u;
        W = (mat == 0) ? Wq1 : (mat == 1) ? Wk1 : (mat == 2) ? Wv1 : Ws1;
        base = OFF_WF + (unsigned)mat * 32768u;
    } else {
        unsigned j = idx - 32768u;
        int mat = j >> 14; rem = j & 16383u;
        W = (mat == 0) ? Wq2 : (mat == 1) ? Wk2 : (mat == 2) ? Wv2 : Ws2;
        base = OFF_WF + 131072u + (unsigned)mat * 65536u;
    }
    int KT = (idx < 32768u) ? 8 : 16;
    int lane = rem & 31;
    int tile = rem >> 5;
    int kt = tile % KT;
    int nt = tile / KT;
    int n = nt * 8 + (lane >> 2);
    int k0 = kt * 16 + (lane & 3) * 2;
    float w00 = W[(unsigned)k0 * HD + n],       w01 = W[(unsigned)(k0 + 1) * HD + n];
    float w10 = W[(unsigned)(k0 + 8) * HD + n], w11 = W[(unsigned)(k0 + 9) * HD + n];
    uint4 out;
    out.x = pack_hi2(w00, w01); out.y = pack_hi2(w10, w11);
    out.z = pack_lo2(w00, w01); out.w = pack_lo2(w10, w11);
    *(uint4*)(g_scratch + base + (unsigned)rem * 4u) = out;
}

// ---------------------------------------------------------------------------
// Kernel 0b: transpose adj -> adjT[b][t][s]
// ---------------------------------------------------------------------------
__global__ void k_adjT(const float* __restrict__ adj) {
    __shared__ float tl[32][33];
    int b = blockIdx.z;
    int s0 = blockIdx.y * 32, t0 = blockIdx.x * 32;
    int x = threadIdx.x, y = threadIdx.y;
#pragma unroll
    for (int i = y; i < 32; i += 8)
        tl[i][x] = adj[(unsigned)(b * NN + s0 + i) * NN + t0 + x];
    __syncthreads();
#pragma unroll
    for (int i = y; i < 32; i += 8)
        g_scratch[OFF_ADJT + (unsigned)(b * NN + t0 + i) * NN + s0 + x] = tl[x][i];
}

// ---------------------------------------------------------------------------
// Kernel 1: base[b,s,j]
// ---------------------------------------------------------------------------
__global__ void k_base(const float* __restrict__ nf, const int* __restrict__ et,
                       const float* __restrict__ emb, const float* __restrict__ W1,
                       const float* __restrict__ b1) {
    int bn = blockIdx.x;
    int j  = threadIdx.x;
    const float* f = nf + bn * 9;
    const float* em = emb + et[bn] * 8;
    float acc = b1[j];
#pragma unroll
    for (int i = 0; i < 9; i++) acc += f[i] * W1[i * HH + j];
#pragma unroll
    for (int i = 0; i < 8; i++) acc += em[i] * W1[(9 + i) * HH + j];
    g_scratch[OFF_BASE + bn * HH + j] = acc;
}

// ---------------------------------------------------------------------------
// Kernel 2: HMMA embed — EXACT R10 version (best measured: 239us)
// ---------------------------------------------------------------------------
#define PK 136
#define SM_BHI   0
#define SM_BLO   34816
#define SM_AHI0  69632
#define SM_ALO0  104448
#define SM_AHI1  139264
#define SM_ALO1  174080
#define SM_W17   208896
#define SM_G1    209408
#define SM_BE1   209920
#define SM_BH    210432
#define SM_BASE0 210944
#define SM_BASE1 211456
#define SM_MASK0 211968
#define SM_MASK1 212480
#define SM_RED   212992
#define EMB_SMEM 215040

__global__ void __launch_bounds__(256, 1)
k_embed_mma(const float* __restrict__ adj, const float* __restrict__ W1,
            const float* __restrict__ g1, const float* __restrict__ be1,
            const float* __restrict__ Wh, const float* __restrict__ bh) {
    extern __shared__ char sm[];
    uint32_t smb = smem_u32(sm);
    float* sW17 = (float*)(sm + SM_W17);
    float* sG1  = (float*)(sm + SM_G1);
    float* sBe1 = (float*)(sm + SM_BE1);
    float* sBh  = (float*)(sm + SM_BH);
    float2* sRed = (float2*)(sm + SM_RED);

    int tid = threadIdx.x;
    int lane = tid & 31, wid = tid >> 5;
    int chunk = blockIdx.x, b = blockIdx.y;

    if (tid < 128) {
        sW17[tid] = W1[17 * HH + tid];
        sG1[tid]  = g1[tid];
        sBe1[tid] = be1[tid];
        sBh[tid]  = bh[tid];
    }

    for (int idx = tid; idx < 16384; idx += 256) {
        int k = idx >> 7, j = idx & 127;
        float w = Wh[idx];
        __nv_bfloat16 h = __float2bfloat16(w);
        __nv_bfloat16 l = __float2bfloat16(w - __bfloat162float(h));
        *(__nv_bfloat16*)(sm + SM_BHI + (j * PK + k) * 2) = h;
        *(__nv_bfloat16*)(sm + SM_BLO + (j * PK + k) * 2) = l;
    }

    int tA = tid >> 1, half = tid & 1;
    int mrow = wid & 3, ncol = wid >> 2;
    int m0 = mrow * 32;
    int rA0 = m0 + (lane >> 2);
    int colbase = ncol * 64;

    float accS[64];
#pragma unroll
    for (int u = 0; u < 64; u++) accS[u] = 0.f;
    float cntA[2] = {0.f, 0.f}, cntB[2] = {0.f, 0.f};

    uint32_t aoff0 = (uint32_t)((m0 + (lane & 15)) * PK + (lane >> 4) * 8) * 2;
    const uint32_t MT_STRIDE = (uint32_t)(16 * PK * 2);
    uint32_t brow = (uint32_t)(((lane & 16) >> 1) + (lane & 7));
    uint32_t bk   = (uint32_t)(((lane >> 3) & 1) * 8);

    int sbeg = chunk * 32;

    float pbase = (tid < 128) ? g_scratch[OFF_BASE + (unsigned)(b * NN + sbeg) * HH + tid] : 0.f;
    float padj  = adj[(unsigned)(b * NN + sbeg) * NN + tA];

    __syncthreads();

    float at_next;
    {
        bool mk = (padj > 0.f) && (padj < 1.0f);
        at_next = mk ? padj : 0.f;
        if (tid < 128) ((float*)(sm + SM_BASE0))[tid] = pbase;
        if (half == 0) ((float*)(sm + SM_MASK0))[tA] = mk ? 1.f : 0.f;
    }
    if (tid < 128) pbase = g_scratch[OFF_BASE + (unsigned)(b * NN + sbeg + 1) * HH + tid];
    padj = adj[(unsigned)(b * NN + sbeg + 1) * NN + tA];
    __syncthreads();

    {
        const float* sBase = (const float*)(sm + SM_BASE0);
        char* AHI = sm + SM_AHI0;
        char* ALO = sm + SM_ALO0;
        int c0 = half * 64;
        float at = at_next;
        float sum = 0.f, ssum = 0.f;
#pragma unroll 4
        for (int j = 0; j < 64; j++) {
            float y = fmaxf(sBase[c0 + j] + at * sW17[c0 + j], 0.f);
            sum += y; ssum += y * y;
        }
        sum  += __shfl_xor_sync(0xffffffffu, sum, 1);
        ssum += __shfl_xor_sync(0xffffffffu, ssum, 1);
        float mean = sum * (1.f / 128.f);
        float rs = rsqrtf(ssum * (1.f / 128.f) - mean * mean + 1e-5f);
#pragma unroll 2
        for (int j2 = 0; j2 < 32; j2++) {
            int j = c0 + j2 * 2;
            float y0 = fmaxf(sBase[j] + at * sW17[j], 0.f);
            float y1 = fmaxf(sBase[j + 1] + at * sW17[j + 1], 0.f);
            float h0 = (y0 - mean) * rs * sG1[j] + sBe1[j];
            float h1 = (y1 - mean) * rs * sG1[j + 1] + sBe1[j + 1];
            uint32_t off = (uint32_t)(tA * PK + j) * 2;
            *(uint32_t*)(AHI + off) = pack_hi2(h0, h1);
            *(uint32_t*)(ALO + off) = pack_lo2(h0, h1);
        }
    }

    for (int si = 0; si < 32; si++) {
        int buf = si & 1, nbuf = buf ^ 1;
        uint32_t aHIu = smb + (buf ? SM_AHI1 : SM_AHI0);
        uint32_t aLOu = smb + (buf ? SM_ALO1 : SM_ALO0);
        float* sMaskC = (float*)(sm + (buf ? SM_MASK1 : SM_MASK0));

        if (si < 31) {
            bool mk = (padj > 0.f) && (padj < 1.0f);
            at_next = mk ? padj : 0.f;
            if (tid < 128) ((float*)(sm + (nbuf ? SM_BASE1 : SM_BASE0)))[tid] = pbase;
            if (half == 0) ((float*)(sm + (nbuf ? SM_MASK1 : SM_MASK0)))[tA] = mk ? 1.f : 0.f;
            if (si < 30) {
                int sn = sbeg + si + 2;
                if (tid < 128) pbase = g_scratch[OFF_BASE + (unsigned)(b * NN + sn) * HH + tid];
                padj = adj[(unsigned)(b * NN + sn) * NN + tA];
            }
        }
        __syncthreads();

        float c[64];
#pragma unroll
        for (int u = 0; u < 64; u++) c[u] = 0.f;

#pragma unroll
        for (int kk = 0; kk < 8; kk++) {
            uint32_t ka = aoff0 + (uint32_t)(kk * 16) * 2;
            uint32_t ah0[4], al0[4], ah1[4], al1[4];
            ldsm_x4(ah0[0], ah0[1], ah0[2], ah0[3], aHIu + ka);
            ldsm_x4(al0[0], al0[1], al0[2], al0[3], aLOu + ka);
            ldsm_x4(ah1[0], ah1[1], ah1[2], ah1[3], aHIu + ka + MT_STRIDE);
            ldsm_x4(al1[0], al1[1], al1[2], al1[3], aLOu + ka + MT_STRIDE);
#pragma unroll
            for (int jp = 0; jp < 4; jp++) {
                uint32_t boff = (uint32_t)((colbase + jp * 16 + brow) * PK + kk * 16 + bk) * 2;
                uint32_t bh4[4], bl4[4];
                ldsm_x4(bh4[0], bh4[1], bh4[2], bh4[3], smb + SM_BHI + boff);
                ldsm_x4(bl4[0], bl4[1], bl4[2], bl4[3], smb + SM_BLO + boff);
                {
                    float* ca = c + (jp * 2) * 4;
                    float* cb = c + (jp * 2 + 1) * 4;
                    mma_bf16(ca, ah0, bh4[0], bh4[1]);
                    mma_bf16(ca, al0, bh4[0], bh4[1]);
                    mma_bf16(ca, ah0, bl4[0], bl4[1]);
                    mma_bf16(cb, ah0, bh4[2], bh4[3]);
                    mma_bf16(cb, al0, bh4[2], bh4[3]);
                    mma_bf16(cb, ah0, bl4[2], bl4[3]);
                }
                {
                    float* ca = c + 32 + (jp * 2) * 4;
                    float* cb = c + 32 + (jp * 2 + 1) * 4;
                    mma_bf16(ca, ah1, bh4[0], bh4[1]);
                    mma_bf16(ca, al1, bh4[0], bh4[1]);
                    mma_bf16(ca, ah1, bl4[0], bl4[1]);
                    mma_bf16(cb, ah1, bh4[2], bh4[3]);
                    mma_bf16(cb, al1, bh4[2], bh4[3]);
                    mma_bf16(cb, ah1, bl4[2], bl4[3]);
                }
            }
        }

        float psumA[2], pssA[2], psumB[2], pssB[2];
#pragma unroll
        for (int mt = 0; mt < 2; mt++) {
            float sum0 = 0.f, ss0 = 0.f, sum1 = 0.f, ss1 = 0.f;
#pragma unroll
            for (int jt = 0; jt < 8; jt++) {
                int col = colbase + jt * 8 + (lane & 3) * 2;
                float b0 = sBh[col], b1 = sBh[col + 1];
                int ci = (mt * 8 + jt) * 4;
                float e0 = fmaxf(c[ci + 0] + b0, 0.f);
                float e1 = fmaxf(c[ci + 1] + b1, 0.f);
                float e2 = fmaxf(c[ci + 2] + b0, 0.f);
                float e3 = fmaxf(c[ci + 3] + b1, 0.f);
                c[ci + 0] = e0; c[ci + 1] = e1; c[ci + 2] = e2; c[ci + 3] = e3;
                sum0 += e0 + e1; ss0 += e0 * e0 + e1 * e1;
                sum1 += e2 + e3; ss1 += e2 * e2 + e3 * e3;
            }
#pragma unroll
            for (int o = 1; o <= 2; o <<= 1) {
                sum0 += __shfl_xor_sync(0xffffffffu, sum0, o);
                ss0  += __shfl_xor_sync(0xffffffffu, ss0, o);
                sum1 += __shfl_xor_sync(0xffffffffu, sum1, o);
                ss1  += __shfl_xor_sync(0xffffffffu, ss1, o);
            }
            psumA[mt] = sum0; pssA[mt] = ss0;
            psumB[mt] = sum1; pssB[mt] = ss1;
        }
        if ((lane & 3) == 0) {
#pragma unroll
            for (int mt = 0; mt < 2; mt++) {
                int rA = rA0 + mt * 16, rB = rA + 8;
                sRed[rA * 2 + ncol] = make_float2(psumA[mt], pssA[mt]);
                sRed[rB * 2 + ncol] = make_float2(psumB[mt], pssB[mt]);
            }
        }
        __syncthreads();

#pragma unroll
        for (int mt = 0; mt < 2; mt++) {
            int rA = rA0 + mt * 16, rB = rA + 8;
            float2 a0 = sRed[rA * 2 + 0], a1 = sRed[rA * 2 + 1];
            float2 b0v = sRed[rB * 2 + 0], b1v = sRed[rB * 2 + 1];
            float mvA = sMaskC[rA], mvB = sMaskC[rB];
            float sumA = a0.x + a1.x, ssA = a0.y + a1.y;
            float sumB = b0v.x + b1v.x, ssB = b0v.y + b1v.y;
            float meanA = sumA * (1.f / 128.f);
            float rsA = rsqrtf(ssA * (1.f / 128.f) - meanA * meanA + 1e-5f) * mvA;
            float meanB = sumB * (1.f / 128.f);
            float rsB = rsqrtf(ssB * (1.f / 128.f) - meanB * meanB + 1e-5f) * mvB;
#pragma unroll
            for (int jt = 0; jt < 8; jt++) {
                int ci = (mt * 8 + jt) * 4;
                accS[ci + 0] += (c[ci + 0] - meanA) * rsA;
                accS[ci + 1] += (c[ci + 1] - meanA) * rsA;
                accS[ci + 2] += (c[ci + 2] - meanB) * rsB;
                accS[ci + 3] += (c[ci + 3] - meanB) * rsB;
            }
            cntA[mt] += mvA; cntB[mt] += mvB;
        }

        if (si < 31) {
            const float* sBase = (const float*)(sm + (nbuf ? SM_BASE1 : SM_BASE0));
            char* AHI = sm + (nbuf ? SM_AHI1 : SM_AHI0);
            char* ALO = sm + (nbuf ? SM_ALO1 : SM_ALO0);
            int c0 = half * 64;
            float at = at_next;
            float sum = 0.f, ssum = 0.f;
#pragma unroll 4
            for (int j = 0; j < 64; j++) {
                float y = fmaxf(sBase[c0 + j] + at * sW17[c0 + j], 0.f);
                sum += y; ssum += y * y;
            }
            sum  += __shfl_xor_sync(0xffffffffu, sum, 1);
            ssum += __shfl_xor_sync(0xffffffffu, ssum, 1);
            float mean = sum * (1.f / 128.f);
            float rs = rsqrtf(ssum * (1.f / 128.f) - mean * mean + 1e-5f);
#pragma unroll 2
            for (int j2 = 0; j2 < 32; j2++) {
                int j = c0 + j2 * 2;
                float y0 = fmaxf(sBase[j] + at * sW17[j], 0.f);
                float y1 = fmaxf(sBase[j + 1] + at * sW17[j + 1], 0.f);
                float h0 = (y0 - mean) * rs * sG1[j] + sBe1[j];
                float h1 = (y1 - mean) * rs * sG1[j + 1] + sBe1[j + 1];
                uint32_t off = (uint32_t)(tA * PK + j) * 2;
                *(uint32_t*)(AHI + off) = pack_hi2(h0, h1);
                *(uint32_t*)(ALO + off) = pack_lo2(h0, h1);
            }
        }
    }

    unsigned pbase_o = OFF_PART + (unsigned)(chunk * 32 + b) * 16384u;
#pragma unroll
    for (int mt = 0; mt < 2; mt++) {
        int rA = rA0 + mt * 16, rB = rA + 8;
#pragma unroll
        for (int jt = 0; jt < 8; jt++) {
            int col = colbase + jt * 8 + (lane & 3) * 2;
            int ci = (mt * 8 + jt) * 4;
            *(float2*)(g_scratch + pbase_o + (unsigned)rA * 128u + col) = make_float2(accS[ci + 0], accS[ci + 1]);
            *(float2*)(g_scratch + pbase_o + (unsigned)rB * 128u + col) = make_float2(accS[ci + 2], accS[ci + 3]);
        }
    }
    if (ncol == 0 && (lane & 3) == 0) {
        unsigned cbase = OFF_CNT + (unsigned)(chunk * 32 + b) * 128u;
#pragma unroll
        for (int mt = 0; mt < 2; mt++) {
            g_scratch[cbase + rA0 + mt * 16]     = cntA[mt];
            g_scratch[cbase + rA0 + mt * 16 + 8] = cntB[mt];
        }
    }
}

// ---------------------------------------------------------------------------
// Kernel 3 (HMMA proj): HIN==128 path fuses the combine step (x0 = gh*Σpart +
// beh*Σcnt) into the X-load; HIN==256 reads X1 directly.
// ---------------------------------------------------------------------------
template <int HIN>
__global__ void __launch_bounds__(256, 1)
k_proj_mma(unsigned xoff, unsigned wfoff,
           const float* __restrict__ bq, const float* __restrict__ bk,
           const float* __restrict__ bv, const float* __restrict__ bs,
           const float* __restrict__ gh, const float* __restrict__ beh) {
    extern __shared__ char sm[];
    constexpr int PJ = HIN + 8;
    constexpr int XHI = 0;
    constexpr int XLO = XHI + 64 * PJ * 2;
    constexpr int KT = HIN / 16;
    constexpr int RSH = (HIN == 128) ? 7 : 8;

    uint32_t smb = smem_u32(sm);
    int tid = threadIdx.x, lane = tid & 31, wid = tid >> 5;
    int r0 = blockIdx.x * 64;
    int my = blockIdx.y;
    const float* bias = (my == 0) ? bq : (my == 1) ? bk : (my == 2) ? bv : bs;
    unsigned outoff   = (my == 0) ? OFF_Q : (my == 1) ? OFF_K : (my == 2) ? OFF_V : OFF_S;
    const float* x = g_scratch + xoff;
    const uint4* BF = (const uint4*)(g_scratch + wfoff + (unsigned)my * (32u * KT * 32u * 4u));

    for (int idx = tid; idx < 64 * HIN; idx += 256) {
        int r = idx >> RSH, k = idx & (HIN - 1);
        float v;
        if (HIN == 128) {
            // fused combine: bt = r0 + r (== b*NN + t), j = k
            unsigned bt = (unsigned)(r0 + r);
            float vv = 0.f, cc = 0.f;
#pragma unroll
            for (int q = 0; q < 4; q++) {
                vv += g_scratch[OFF_PART + (unsigned)q * 524288u + bt * 128u + k];
                cc += g_scratch[OFF_CNT + (unsigned)q * 4096u + bt];
            }
            v = gh[k] * vv + beh[k] * cc;
        } else {
            v = x[(unsigned)(r0 + r) * HIN + k];
        }
        __nv_bfloat16 h = __float2bfloat16(v);
        __nv_bfloat16 l = __float2bfloat16(v - __bfloat162float(h));
        *(__nv_bfloat16*)(sm + XHI + (r * PJ + k) * 2) = h;
        *(__nv_bfloat16*)(sm + XLO + (r * PJ + k) * 2) = l;
    }
    __syncthreads();

    int mrow = wid & 3, ncol = wid >> 2;
    int m0 = mrow * 16;
    uint32_t aoff = (uint32_t)((m0 + (lane & 15)) * PJ + (lane >> 4) * 8) * 2;

    float c[64];
#pragma unroll
    for (int u = 0; u < 64; u++) c[u] = 0.f;

#pragma unroll
    for (int kk = 0; kk < KT; kk++) {
        uint32_t ah[4], al[4];
        uint32_t ka = aoff + (uint32_t)(kk * 16) * 2;
        ldsm_x4(ah[0], ah[1], ah[2], ah[3], smb + XHI + ka);
        ldsm_x4(al[0], al[1], al[2], al[3], smb + XLO + ka);
#pragma unroll
        for (int jp = 0; jp < 16; jp++) {
            int nt = ncol * 16 + jp;
            uint4 f = BF[(unsigned)(nt * KT + kk) * 32u + lane];
            float* cj = c + jp * 4;
            mma_bf16(cj, ah, f.x, f.y);
            mma_bf16(cj, al, f.x, f.y);
            mma_bf16(cj, ah, f.z, f.w);
        }
    }

    int rA = r0 + m0 + (lane >> 2);
    int rB = rA + 8;
#pragma unroll
    for (int jp = 0; jp < 16; jp++) {
        int col = ncol * 128 + jp * 8 + (lane & 3) * 2;
        float b0 = bias[col], b1 = bias[col + 1];
        *(float2*)(g_scratch + outoff + (unsigned)rA * HD + col) =
            make_float2(c[jp * 4 + 0] + b0, c[jp * 4 + 1] + b1);
        *(float2*)(g_scratch + outoff + (unsigned)rB * HD + col) =
            make_float2(c[jp * 4 + 2] + b0, c[jp * 4 + 3] + b1);
    }
}

// ---------------------------------------------------------------------------
// Kernel 4 (HMMA attention, 256 threads / 8 warps — 2 warps/SMSP):
// Phase B: 8 warps cover all 128 t rows in ONE pass (warp tile 16 x 128).
// Phase C: 8 warps x 16 rows (c[32]).
// ---------------------------------------------------------------------------
#define AQHI 0
#define AQLO 18432
#define AKHI 36864
#define AKLO 55296
#define AVHI 73728
#define AVLO 91136
#define APHI 108544
#define APLO 143360
#define AQE  178176
#define ABETA 178688
#define AWE  179200
#define ATTN_SMEM 179456

__global__ void __launch_bounds__(256, 1)
k_attn_mma(const float* __restrict__ we, unsigned outoff) {
    extern __shared__ char sm[];
    uint32_t smb = smem_u32(sm);
    float* sQE   = (float*)(sm + AQE);
    float* sBeta = (float*)(sm + ABETA);
    float* sWe   = (float*)(sm + AWE);

    int h = blockIdx.x, b = blockIdx.y;
    int tid = threadIdx.x, lane = tid & 31, wid = tid >> 5;
    const float* q = g_scratch + OFF_Q;
    const float* k = g_scratch + OFF_K;
    const float* v = g_scratch + OFF_V;
    const float* skip = g_scratch + OFF_S;
    const float* adjT = g_scratch + OFF_ADJT + (unsigned)b * NN * NN;
    float* xout = g_scratch + outoff;

    if (tid < 64) sWe[tid] = we[h * DH + tid];
    for (int idx = tid; idx < 8192; idx += 256) {
        int r = idx >> 6, d = idx & 63;
        unsigned g = ((unsigned)(b * NN + r) * NHEADS + h) * DH + d;
        float qv = q[g], kv = k[g], vv = v[g];
        __nv_bfloat16 qh = __float2bfloat16(qv);
        __nv_bfloat16 kh = __float2bfloat16(kv);
        __nv_bfloat16 vh = __float2bfloat16(vv);
        *(__nv_bfloat16*)(sm + AQHI + (r * 72 + d) * 2) = qh;
        *(__nv_bfloat16*)(sm + AQLO + (r * 72 + d) * 2) = __float2bfloat16(qv - __bfloat162float(qh));
        *(__nv_bfloat16*)(sm + AKHI + (r * 72 + d) * 2) = kh;
        *(__nv_bfloat16*)(sm + AKLO + (r * 72 + d) * 2) = __float2bfloat16(kv - __bfloat162float(kh));
        *(__nv_bfloat16*)(sm + AVHI + (d * PK + r) * 2) = vh;
        *(__nv_bfloat16*)(sm + AVLO + (d * PK + r) * 2) = __float2bfloat16(vv - __bfloat162float(vh));
    }
    __syncthreads();

    if (tid < 128) {   // qe[t]
        int t = tid;
        float acc = 0.f;
#pragma unroll 8
        for (int d = 0; d < 64; d++) {
            float hv = __bfloat162float(*(__nv_bfloat16*)(sm + AQHI + (t * 72 + d) * 2));
            float lv = __bfloat162float(*(__nv_bfloat16*)(sm + AQLO + (t * 72 + d) * 2));
            acc += (hv + lv) * sWe[d];
        }
        sQE[t] = acc;
    }
    __syncthreads();

    uint32_t brow = (uint32_t)(((lane & 16) >> 1) + (lane & 7));
    uint32_t bk   = (uint32_t)(((lane >> 3) & 1) * 8);
    const float scale = 0.125f;

    // ---- Phase B: 8 warps, warp tile 16 t-rows x 128 s ----
    {
        int m0 = wid * 16;
        int r0 = m0 + (lane >> 2), r1 = r0 + 8;
        uint32_t aoff = (uint32_t)((m0 + (lane & 15)) * 72 + (lane >> 4) * 8) * 2;

        float c[64];
#pragma unroll
        for (int u = 0; u < 64; u++) c[u] = 0.f;

#pragma unroll
        for (int kk = 0; kk < 4; kk++) {
            uint32_t ka = aoff + (uint32_t)(kk * 16) * 2;
            uint32_t ah[4], al[4];
            ldsm_x4(ah[0], ah[1], ah[2], ah[3], smb + AQHI + ka);
            ldsm_x4(al[0], al[1], al[2], al[3], smb + AQLO + ka);
#pragma unroll
            for (int jp = 0; jp < 8; jp++) {
                uint32_t boff = (uint32_t)((jp * 16 + brow) * 72 + kk * 16 + bk) * 2;
                uint32_t bh4[4], bl4[4];
                ldsm_x4(bh4[0], bh4[1], bh4[2], bh4[3], smb + AKHI + boff);
                ldsm_x4(bl4[0], bl4[1], bl4[2], bl4[3], smb + AKLO + boff);
                float* ca = c + (jp * 2) * 4;
                float* cb = c + (jp * 2 + 1) * 4;
                mma_bf16(ca, ah, bh4[0], bh4[1]);
                mma_bf16(cb, ah, bh4[2], bh4[3]);
                mma_bf16(ca, al, bh4[0], bh4[1]);
                mma_bf16(cb, al, bh4[2], bh4[3]);
                mma_bf16(ca, ah, bl4[0], bl4[1]);
                mma_bf16(cb, ah, bl4[2], bl4[3]);
            }
        }

        float av[64];
        float qe0 = sQE[r0], qe1 = sQE[r1];
#pragma unroll
        for (int jt = 0; jt < 16; jt++) {
            int col = jt * 8 + (lane & 3) * 2;
            float2 a0 = *(const float2*)(adjT + (unsigned)r0 * NN + col);
            float2 a1 = *(const float2*)(adjT + (unsigned)r1 * NN + col);
            int ci = jt * 4;
            bool m00 = (a0.x > 0.f) && (a0.x < 1.0f);
            bool m01 = (a0.y > 0.f) && (a0.y < 1.0f);
            bool m10 = (a1.x > 0.f) && (a1.x < 1.0f);
            bool m11 = (a1.y > 0.f) && (a1.y < 1.0f);
            float v00 = m00 ? a0.x : 0.f, v01 = m01 ? a0.y : 0.f;
            float v10 = m10 ? a1.x : 0.f, v11 = m11 ? a1.y : 0.f;
            av[ci + 0] = v00; av[ci + 1] = v01; av[ci + 2] = v10; av[ci + 3] = v11;
            c[ci + 0] = m00 ? (c[ci + 0] + v00 * qe0) * scale : -1e30f;
            c[ci + 1] = m01 ? (c[ci + 1] + v01 * qe0) * scale : -1e30f;
            c[ci + 2] = m10 ? (c[ci + 2] + v10 * qe1) * scale : -1e30f;
            c[ci + 3] = m11 ? (c[ci + 3] + v11 * qe1) * scale : -1e30f;
        }

        float mx0 = -1e30f, mx1 = -1e30f;
#pragma unroll
        for (int jt = 0; jt < 16; jt++) {
            mx0 = fmaxf(mx0, fmaxf(c[jt * 4 + 0], c[jt * 4 + 1]));
            mx1 = fmaxf(mx1, fmaxf(c[jt * 4 + 2], c[jt * 4 + 3]));
        }
#pragma unroll
        for (int o = 1; o <= 2; o <<= 1) {
            mx0 = fmaxf(mx0, __shfl_xor_sync(0xffffffffu, mx0, o));
            mx1 = fmaxf(mx1, __shfl_xor_sync(0xffffffffu, mx1, o));
        }

        float sw0 = 0.f, swa0 = 0.f, sw1 = 0.f, swa1 = 0.f;
#pragma unroll
        for (int jt = 0; jt < 16; jt++) {
            int ci = jt * 4;
            float w0 = (c[ci + 0] > -1e29f) ? __expf(c[ci + 0] - mx0) : 0.f;
            float w1 = (c[ci + 1] > -1e29f) ? __expf(c[ci + 1] - mx0) : 0.f;
            float w2 = (c[ci + 2] > -1e29f) ? __expf(c[ci + 2] - mx1) : 0.f;
            float w3 = (c[ci + 3] > -1e29f) ? __expf(c[ci + 3] - mx1) : 0.f;
            c[ci + 0] = w0; c[ci + 1] = w1; c[ci + 2] = w2; c[ci + 3] = w3;
            sw0 += w0 + w1; swa0 += w0 * av[ci + 0] + w1 * av[ci + 1];
            sw1 += w2 + w3; swa1 += w2 * av[ci + 2] + w3 * av[ci + 3];
        }
#pragma unroll
        for (int o = 1; o <= 2; o <<= 1) {
            sw0  += __shfl_xor_sync(0xffffffffu, sw0, o);
            swa0 += __shfl_xor_sync(0xffffffffu, swa0, o);
            sw1  += __shfl_xor_sync(0xffffffffu, sw1, o);
            swa1 += __shfl_xor_sync(0xffffffffu, swa1, o);
        }
        float inv0 = 1.f / fmaxf(sw0, 1e-16f);
        float inv1 = 1.f / fmaxf(sw1, 1e-16f);
        if ((lane & 3) == 0) {
            sBeta[r0] = swa0 * inv0;
            sBeta[r1] = swa1 * inv1;
        }

#pragma unroll
        for (int jt = 0; jt < 16; jt++) {
            int col = jt * 8 + (lane & 3) * 2;
            int ci = jt * 4;
            float a00 = c[ci + 0] * inv0, a01 = c[ci + 1] * inv0;
            float a10 = c[ci + 2] * inv1, a11 = c[ci + 3] * inv1;
            uint32_t o0 = (uint32_t)(r0 * PK + col) * 2;
            uint32_t o1 = (uint32_t)(r1 * PK + col) * 2;
            *(uint32_t*)(sm + APHI + o0) = pack_hi2(a00, a01);
            *(uint32_t*)(sm + APLO + o0) = pack_lo2(a00, a01);
            *(uint32_t*)(sm + APHI + o1) = pack_hi2(a10, a11);
            *(uint32_t*)(sm + APLO + o1) = pack_lo2(a10, a11);
        }
    }
    __syncthreads();

    // ---- Phase C: 8 warps x 16 rows, O = P V^T ----
    {
        int m0 = wid * 16;
        int r0 = m0 + (lane >> 2);
        uint32_t aoff = (uint32_t)((m0 + (lane & 15)) * PK + (lane >> 4) * 8) * 2;

        float c[32];
#pragma unroll
        for (int u = 0; u < 32; u++) c[u] = 0.f;

#pragma unroll
        for (int kk = 0; kk < 8; kk++) {
            uint32_t ka = aoff + (uint32_t)(kk * 16) * 2;
            uint32_t ah[4], al[4];
            ldsm_x4(ah[0], ah[1], ah[2], ah[3], smb + APHI + ka);
            ldsm_x4(al[0], al[1], al[2], al[3], smb + APLO + ka);
#pragma unroll
            for (int jp = 0; jp < 4; jp++) {
                uint32_t boff = (uint32_t)((jp * 16 + brow) * PK + kk * 16 + bk) * 2;
                uint32_t bh4[4], bl4[4];
                ldsm_x4(bh4[0], bh4[1], bh4[2], bh4[3], smb + AVHI + boff);
                ldsm_x4(bl4[0], bl4[1], bl4[2], bl4[3], smb + AVLO + boff);
                float* ca = c + (jp * 2) * 4;
                float* cb = c + (jp * 2 + 1) * 4;
                mma_bf16(ca, ah, bh4[0], bh4[1]);
                mma_bf16(cb, ah, bh4[2], bh4[3]);
                mma_bf16(ca, al, bh4[0], bh4[1]);
                mma_bf16(cb, al, bh4[2], bh4[3]);
                mma_bf16(ca, ah, bl4[0], bl4[1]);
                mma_bf16(cb, ah, bl4[2], bl4[3]);
            }
        }

        int rA = r0, rB = r0 + 8;
        float betaA = sBeta[rA], betaB = sBeta[rB];
#pragma unroll
        for (int jt = 0; jt < 8; jt++) {
            int col = jt * 8 + (lane & 3) * 2;
            float we0 = sWe[col], we1 = sWe[col + 1];
            int ci = jt * 4;
            unsigned iA = (unsigned)(b * NN + rA) * HD + h * DH + col;
            unsigned iB = (unsigned)(b * NN + rB) * HD + h * DH + col;
            float2 skA = *(const float2*)(skip + iA);
            float2 skB = *(const float2*)(skip + iB);
            float oA0 = fmaxf(c[ci + 0] + betaA * we0 + skA.x, 0.f);
            float oA1 = fmaxf(c[ci + 1] + betaA * we1 + skA.y, 0.f);
            float oB0 = fmaxf(c[ci + 2] + betaB * we0 + skB.x, 0.f);
            float oB1 = fmaxf(c[ci + 3] + betaB * we1 + skB.y, 0.f);
            *(float2*)(xout + iA) = make_float2(oA0, oA1);
            *(float2*)(xout + iB) = make_float2(oB0, oB1);
        }
    }
}

// ---------------------------------------------------------------------------
// Kernel 5: gather agent rows
// ---------------------------------------------------------------------------
__global__ void k_gather(const int* __restrict__ agent, float* __restrict__ out) {
    int b = blockIdx.x, j = threadIdx.x;
    out[b * HD + j] = g_scratch[OFF_X2 + (unsigned)(b * NN + agent[b]) * HD + j];
}

// ---------------------------------------------------------------------------
extern "C" void kernel_launch(void* const* d_in, const int* in_sizes, int n_in,
                              void* d_out, int out_size) {
    const float* node_feat = (const float*)d_in[0];
    const int*   entity_type = (const int*)d_in[1];
    const float* adj = (const float*)d_in[2];
    const int*   agent_id = (const int*)d_in[3];
    const float* emb = (const float*)d_in[4];
    const float* W1 = (const float*)d_in[5];
    const float* b1 = (const float*)d_in[6];
    const float* g1 = (const float*)d_in[7];
    const float* be1 = (const float*)d_in[8];
    const float* Wh = (const float*)d_in[9];
    const float* bh = (const float*)d_in[10];
    const float* gh = (const float*)d_in[11];
    const float* beh = (const float*)d_in[12];
    const float* Wq1 = (const float*)d_in[13];
    const float* bq1 = (const float*)d_in[14];
    const float* Wk1 = (const float*)d_in[15];
    const float* bk1 = (const float*)d_in[16];
    const float* Wv1 = (const float*)d_in[17];
    const float* bv1 = (const float*)d_in[18];
    const float* We1 = (const float*)d_in[19];
    const float* Ws1 = (const float*)d_in[20];
    const float* bs1 = (const float*)d_in[21];
    const float* Wq2 = (const float*)d_in[22];
    const float* bq2 = (const float*)d_in[23];
    const float* Wk2 = (const float*)d_in[24];
    const float* bk2 = (const float*)d_in[25];
    const float* Wv2 = (const float*)d_in[26];
    const float* bv2 = (const float*)d_in[27];
    const float* We2 = (const float*)d_in[28];
    const float* Ws2 = (const float*)d_in[29];
    const float* bs2 = (const float*)d_in[30];

    constexpr int PROJ128_SMEM = 2 * 64 * 136 * 2;   // 34816
    constexpr int PROJ256_SMEM = 2 * 64 * 264 * 2;   // 67584

    cudaFuncSetAttribute(k_embed_mma, cudaFuncAttributeMaxDynamicSharedMemorySize, EMB_SMEM);
    cudaFuncSetAttribute(k_proj_mma<128>, cudaFuncAttributeMaxDynamicSharedMemorySize, PROJ128_SMEM);
    cudaFuncSetAttribute(k_proj_mma<256>, cudaFuncAttributeMaxDynamicSharedMemorySize, PROJ256_SMEM);
    cudaFuncSetAttribute(k_attn_mma, cudaFuncAttributeMaxDynamicSharedMemorySize, ATTN_SMEM);

    k_wsplit<<<384, 256>>>(Wq1, Wk1, Wv1, Ws1, Wq2, Wk2, Wv2, Ws2);
    k_adjT<<<dim3(4, 4, BB), dim3(32, 8)>>>(adj);
    k_base<<<BB * NN, 128>>>(node_feat, entity_type, emb, W1, b1);
    k_embed_mma<<<dim3(4, BB), 256, EMB_SMEM>>>(adj, W1, g1, be1, Wh, bh);

    // combine fused into k_proj_mma<128>
    k_proj_mma<128><<<dim3(64, 4), 256, PROJ128_SMEM>>>(OFF_X0, OFF_WF, bq1, bk1, bv1, bs1, gh, beh);
    k_attn_mma<<<dim3(NHEADS, BB), 256, ATTN_SMEM>>>(We1, OFF_X1);

    k_proj_mma<256><<<dim3(64, 4), 256, PROJ256_SMEM>>>(OFF_X1, OFF_WF + 131072u, bq2, bk2, bv2, bs2, gh, beh);
    k_attn_mma<<<dim3(NHEADS, BB), 256, ATTN_SMEM>>>(We2, OFF_X2);

    k_gather<<<BB, 256>>>(agent_id, (float*)d_out);
}